// round 16
// baseline (speedup 1.0000x reference)
#include <cuda_runtime.h>
#include <cuda_fp16.h>
#include <math.h>

#define B_TOT 32768
#define F_TOT 512
#define H_TOT 10

#define THREADS 512          // 16 warps; warp w covers features [32w, 32w+32)
#define NWARP (THREADS / 32)
#define CHUNK 32             // batches per block
#define NB 4                 // batches per inner group (2 half2 pairs)

__device__ __forceinline__ __half2 tanh2_fast(__half2 v) {
    unsigned a = *reinterpret_cast<unsigned*>(&v), r;
    asm("tanh.approx.f16x2 %0, %1;" : "=r"(r) : "r"(a));
    return *reinterpret_cast<__half2*>(&r);
}

__device__ __forceinline__ float warp_sum(float v) {
#pragma unroll
    for (int off = 16; off > 0; off >>= 1)
        v += __shfl_xor_sync(0xFFFFFFFFu, v, off);
    return v;
}

// ---------------------------------------------------------------------------
// Converged optimum (measured 49.2us, ~96% of the MUFU tanh service floor).
// Lane owns one feature; all params in registers (W1/b1 broadcast half2,
// w2*softplus fp32). Inner loop per h: 2 HFMA2 arg + 2 tanh2 (MUFU) +
// 2 cvt-pair + 4 fp32 FFMA acc. Folded 11-SHFL reduction per 4-batch group.
// ---------------------------------------------------------------------------
__global__ __launch_bounds__(THREADS, 2)
void neural_unilasso_kernel(const float* __restrict__ x,
                            const float* __restrict__ W1,
                            const float* __restrict__ b1,
                            const float* __restrict__ W2,
                            const float* __restrict__ b2,
                            const float* __restrict__ theta,
                            const float* __restrict__ bias,
                            float* __restrict__ y,
                            float* __restrict__ y_theta) {
    __shared__ float part[CHUNK * 17];   // [batch][warp], padded stride
    __shared__ float s_red[NWARP];
    __shared__ float s_base;

    const int tid  = threadIdx.x;
    const int lane = tid & 31;
    const int warp = tid >> 5;
    const int f    = warp * 32 + lane;   // THREADS == F_TOT

    // ---- prologue: params + softplus + csum ----
    const float th = theta[f];
    const float st = log1pf(expf(th));           // softplus
    if (blockIdx.x == 0) y_theta[f] = st;        // nn_theta output

    __half2 w1h[H_TOT], b1h[H_TOT];
    float w2r[H_TOT];
#pragma unroll
    for (int h = 0; h < H_TOT; h++) {
        float w1 = __ldg(&W1[f * H_TOT + h]);
        float bb = __ldg(&b1[f * H_TOT + h]);
        w1h[h] = __floats2half2_rn(w1, w1);
        b1h[h] = __floats2half2_rn(bb, bb);
        w2r[h] = __ldg(&W2[f * H_TOT + h]) * st; // fp32, exact scaling
    }
    {
        float c = warp_sum(b2[f] * st);
        if (lane == 0) s_red[warp] = c;
        __syncthreads();
        if (tid == 0) {
            float s = bias[0];
#pragma unroll
            for (int w = 0; w < NWARP; w++) s += s_red[w];
            s_base = s;
        }
        __syncthreads();
    }

    const int bchunk = blockIdx.x * CHUNK;
    const float* xp = x + (size_t)bchunk * F_TOT + f;

    // depth-1 prefetch
    float xc0 = __ldg(xp + 0 * F_TOT);
    float xc1 = __ldg(xp + 1 * F_TOT);
    float xc2 = __ldg(xp + 2 * F_TOT);
    float xc3 = __ldg(xp + 3 * F_TOT);

#pragma unroll 1
    for (int g = 0; g < CHUNK; g += NB) {
        float xn0, xn1, xn2, xn3;
        if (g + NB < CHUNK) {
            xn0 = __ldg(xp + (size_t)(g + NB + 0) * F_TOT);
            xn1 = __ldg(xp + (size_t)(g + NB + 1) * F_TOT);
            xn2 = __ldg(xp + (size_t)(g + NB + 2) * F_TOT);
            xn3 = __ldg(xp + (size_t)(g + NB + 3) * F_TOT);
        }

        const __half2 x01 = __floats2half2_rn(xc0, xc1);
        const __half2 x23 = __floats2half2_rn(xc2, xc3);

        float a0 = 0.f, a1 = 0.f, a2 = 0.f, a3 = 0.f;
#pragma unroll
        for (int h = 0; h < H_TOT; h++) {
            __half2 p01 = __hfma2(x01, w1h[h], b1h[h]);
            __half2 p23 = __hfma2(x23, w1h[h], b1h[h]);
            __half2 t01 = tanh2_fast(p01);
            __half2 t23 = tanh2_fast(p23);
            float2 f01 = __half22float2(t01);
            float2 f23 = __half22float2(t23);
            a0 = fmaf(f01.x, w2r[h], a0);
            a1 = fmaf(f01.y, w2r[h], a1);
            a2 = fmaf(f23.x, w2r[h], a2);
            a3 = fmaf(f23.y, w2r[h], a3);
        }

        // folded 4-accumulator warp reduction (11 SHFL)
        a0 += __shfl_xor_sync(0xFFFFFFFFu, a0, 16);
        a1 += __shfl_xor_sync(0xFFFFFFFFu, a1, 16);
        a2 += __shfl_xor_sync(0xFFFFFFFFu, a2, 16);
        a3 += __shfl_xor_sync(0xFFFFFFFFu, a3, 16);
        a0 += __shfl_xor_sync(0xFFFFFFFFu, a0, 8);
        a1 += __shfl_xor_sync(0xFFFFFFFFu, a1, 8);
        a2 += __shfl_xor_sync(0xFFFFFFFFu, a2, 8);
        a3 += __shfl_xor_sync(0xFFFFFFFFu, a3, 8);
        int q = (lane >> 3) & 3;                 // quarter selects its accumulator
        float c = (q == 0) ? a0 : (q == 1) ? a1 : (q == 2) ? a2 : a3;
        c += __shfl_xor_sync(0xFFFFFFFFu, c, 4);
        c += __shfl_xor_sync(0xFFFFFFFFu, c, 2);
        c += __shfl_xor_sync(0xFFFFFFFFu, c, 1);
        if ((lane & 7) == 0)
            part[(g + q) * 17 + warp] = c;

        xc0 = xn0; xc1 = xn1; xc2 = xn2; xc3 = xn3;
    }
    __syncthreads();

    if (tid < CHUNK) {
        float s = s_base;
#pragma unroll
        for (int w = 0; w < NWARP; w++) s += part[tid * 17 + w];
        y[bchunk + tid] = s;
    }
}

// ---------------------------------------------------------------------------
// kernel_launch: inputs in setup_inputs order:
//   0:x (B,F)  1:W1 (F,H)  2:b1 (F,H)  3:W2 (F,H)  4:b2 (F)  5:theta (F)  6:bias (1)
// output: y_pred (B) then nn_theta (F), fp32.
// ---------------------------------------------------------------------------
extern "C" void kernel_launch(void* const* d_in, const int* in_sizes, int n_in,
                              void* d_out, int out_size) {
    const float* x     = (const float*)d_in[0];
    const float* W1    = (const float*)d_in[1];
    const float* b1    = (const float*)d_in[2];
    const float* W2    = (const float*)d_in[3];
    const float* b2    = (const float*)d_in[4];
    const float* theta = (const float*)d_in[5];
    const float* bias  = (const float*)d_in[6];
    float* out = (float*)d_out;

    neural_unilasso_kernel<<<B_TOT / CHUNK, THREADS>>>(
        x, W1, b1, W2, b2, theta, bias, out, out + B_TOT);
}